// round 16
// baseline (speedup 1.0000x reference)
#include <cuda_runtime.h>
#include <math.h>

#define N_TOK 4096
#define D_DIM 2048
#define N_EXP 8
#define TOPK  2
#define CAP   512
#define PITCH 2052                 // padded W smem row (floats)
#define BLK1  768                  // 24 warps: 16 GEMM + 8 fill
#define GRID1 128                  // 1 block/SM, single balanced wave

// Scratch (static device globals — no allocation)
__device__ unsigned int g_rec[N_TOK];     // packed: c0|lp0<<3|c1<<8|lp1<<11
__device__ int g_counts[16 * GRID1];      // [pair][block] counts

__device__ __forceinline__ unsigned long long fma2(
        unsigned long long a, unsigned long long b, unsigned long long c) {
    unsigned long long d;
    asm("fma.rn.f32x2 %0, %1, %2, %3;" : "=l"(d) : "l"(a), "l"(b), "l"(c));
    return d;
}

// ---------------------------------------------------------------------------
// Kernel 1 (warp-specialized, R13-proven + ballot epilogue):
//   warps 0-15 : logits GEMM (2 tok/warp), top-2 + softmax, gates/indices;
//                lane0 parks choices in smem.
//   warps 16-23: zero this block's 512 KB dispatcher slice concurrently.
//   epilogue   : warp 0 computes within-block (k,e) prefixes via ballot and
//                publishes packed per-token records + per-block counts.
// ---------------------------------------------------------------------------
__global__ __launch_bounds__(BLK1) void k_fused(
        const float* __restrict__ x,
        const float* __restrict__ W,
        float* __restrict__ out) {
    __shared__ float wt[N_EXP * PITCH];   // 65.7 KB
    __shared__ unsigned char s_c0[32], s_c1[32];

    int tid  = threadIdx.x;
    int lane = tid & 31;
    int wrp  = tid >> 5;
    int bid  = blockIdx.x;

    // stage ALL of W transposed: wt[e][d]  (all 24 warps help)
    for (int idx = tid; idx < D_DIM * N_EXP; idx += BLK1) {
        int d = idx >> 3;
        int e = idx & 7;
        wt[e * PITCH + d] = W[idx];
    }
    __syncthreads();

    if (wrp >= 16) {
        // ---------------- fill warps: zero 64 KB each ----------------
        int f = wrp - 16;
        float4* z4 = reinterpret_cast<float4*>(out);
        size_t base = (size_t)bid * 32768 + f * 4096 + lane;   // f4 units
        const float4 zero = make_float4(0.f, 0.f, 0.f, 0.f);
        #pragma unroll 8
        for (int i = 0; i < 128; i++)
            z4[base + i * 32] = zero;
    } else {
        // ---------------- GEMM warps: 2 tokens each ----------------
        int t0 = (bid * 16 + wrp) * 2;
        const ulonglong2* xr0 = reinterpret_cast<const ulonglong2*>(x) + (size_t)t0 * (D_DIM / 4);
        const ulonglong2* xr1 = xr0 + (D_DIM / 4);

        unsigned long long acc0[N_EXP] = {};
        unsigned long long acc1[N_EXP] = {};

        // double-buffered 2-j prefetch: 4 LDG.128 in flight per warp
        ulonglong2 xa[2][2], xb[2][2];
        xa[0][0] = xr0[lane];      xb[0][0] = xr1[lane];
        xa[0][1] = xr0[32 + lane]; xb[0][1] = xr1[32 + lane];

        #pragma unroll
        for (int jj = 0; jj < 8; jj++) {
            int cur = jj & 1, nxt = cur ^ 1;
            if (jj < 7) {
                int j2 = (jj + 1) * 2;
                xa[nxt][0] = xr0[(j2    ) * 32 + lane];
                xb[nxt][0] = xr1[(j2    ) * 32 + lane];
                xa[nxt][1] = xr0[(j2 + 1) * 32 + lane];
                xb[nxt][1] = xr1[(j2 + 1) * 32 + lane];
            }
            #pragma unroll
            for (int u = 0; u < 2; u++) {
                int dbase = ((jj * 2 + u) * 32 + lane) * 4;
                #pragma unroll
                for (int e = 0; e < N_EXP; e++) {
                    ulonglong2 w = *reinterpret_cast<const ulonglong2*>(&wt[e * PITCH + dbase]);
                    acc0[e] = fma2(xa[cur][u].x, w.x, acc0[e]);
                    acc0[e] = fma2(xa[cur][u].y, w.y, acc0[e]);
                    acc1[e] = fma2(xb[cur][u].x, w.x, acc1[e]);
                    acc1[e] = fma2(xb[cur][u].y, w.y, acc1[e]);
                }
            }
        }

        // horizontal add + butterfly reduce
        float logit[2][N_EXP];
        #pragma unroll
        for (int e = 0; e < N_EXP; e++) {
            float s0 = __uint_as_float((unsigned int)(acc0[e] & 0xffffffffull)) +
                       __uint_as_float((unsigned int)(acc0[e] >> 32));
            float s1 = __uint_as_float((unsigned int)(acc1[e] & 0xffffffffull)) +
                       __uint_as_float((unsigned int)(acc1[e] >> 32));
            #pragma unroll
            for (int off = 16; off > 0; off >>= 1) {
                s0 += __shfl_xor_sync(0xffffffffu, s0, off);
                s1 += __shfl_xor_sync(0xffffffffu, s1, off);
            }
            logit[0][e] = s0;
            logit[1][e] = s1;
        }

        if (lane == 0) {
            float* gate = out + (size_t)N_TOK * N_EXP * CAP;
            float* idxf = gate + N_TOK * TOPK;
            #pragma unroll
            for (int t = 0; t < 2; t++) {
                int tok = t0 + t;
                float best = -INFINITY, sec = -INFINITY;
                int bi = 0, si = 0;
                #pragma unroll
                for (int e = 0; e < N_EXP; e++) {
                    float v = logit[t][e];
                    if (v > best)     { sec = best; si = bi; best = v; bi = e; }
                    else if (v > sec) { sec = v;    si = e; }
                }
                float g0 = 1.0f / (1.0f + expf(sec - best));
                gate[tok * 2 + 0] = g0;
                gate[tok * 2 + 1] = 1.0f - g0;
                idxf[tok * 2 + 0] = (float)bi;
                idxf[tok * 2 + 1] = (float)si;
                int l = 2 * wrp + t;          // token index within block
                s_c0[l] = (unsigned char)bi;
                s_c1[l] = (unsigned char)si;
            }
        }
    }

    // ---- ballot epilogue: within-block prefixes + per-block counts ----
    __syncthreads();   // fill warps arrive early; GEMM warps ~together
    if (wrp == 0) {
        int c0 = s_c0[lane];                  // token bid*32+lane, k=0 choice
        int c1 = s_c1[lane];                  // k=1 choice
        unsigned int lt = (1u << lane) - 1u;
        int lp0 = 0, lp1 = 0, cnt0 = 0, cnt1 = 0;
        #pragma unroll
        for (int e = 0; e < N_EXP; e++) {
            unsigned int m0 = __ballot_sync(0xffffffffu, c0 == e);
            unsigned int m1 = __ballot_sync(0xffffffffu, c1 == e);
            if (c0 == e) lp0 = __popc(m0 & lt);
            if (c1 == e) lp1 = __popc(m1 & lt);
            if (lane == e) { cnt0 = __popc(m0); cnt1 = __popc(m1); }
        }
        g_rec[bid * 32 + lane] =
            (unsigned int)c0 | ((unsigned int)lp0 << 3) |
            ((unsigned int)c1 << 8) | ((unsigned int)lp1 << 11);
        if (lane < 8)  g_counts[lane * GRID1 + bid] = cnt0;        // pairs 0-7  (k=0)
        if (lane < 8)  g_counts[(8 + lane) * GRID1 + bid] = cnt1;  // pairs 8-15 (k=1)
    }
}

// ---------------------------------------------------------------------------
// Kernel 2 (scatter-light): 16 blocks, one per (k,e) pair.
// 128-block count prefix from the 8 KB g_counts array, then scatter the
// 1.0f entries using packed per-token records. No 4096-token scan.
// ---------------------------------------------------------------------------
__global__ __launch_bounds__(256) void k_scatter(float* __restrict__ out) {
    int p = blockIdx.x;            // pair
    int k = p >> 3;
    int e = p & 7;
    int tid  = threadIdx.x;
    int lane = tid & 31;
    int w    = tid >> 5;

    __shared__ int bpre[GRID1];
    __shared__ int wsum[4];

    int v = 0, inc = 0;
    if (tid < GRID1) {
        v = g_counts[p * GRID1 + tid];
        inc = v;
        #pragma unroll
        for (int off = 1; off < 32; off <<= 1) {
            int u = __shfl_up_sync(0xffffffffu, inc, off);
            if (lane >= off) inc += u;
        }
        if (lane == 31) wsum[w] = inc;
    }
    __syncthreads();
    if (tid == 0) {
        int a = 0;
        #pragma unroll
        for (int i = 0; i < 4; i++) { int t = wsum[i]; wsum[i] = a; a += t; }
    }
    __syncthreads();
    if (tid < GRID1) bpre[tid] = wsum[w] + inc - v;   // exclusive block prefix
    __syncthreads();

    #pragma unroll
    for (int i = 0; i < 16; i++) {
        int tok = i * 256 + tid;
        unsigned int r = g_rec[tok];
        int c  = k ? (int)((r >> 8) & 7)   : (int)(r & 7);
        int lp = k ? (int)((r >> 11) & 31) : (int)((r >> 3) & 31);
        if (c == e) {
            int slot = bpre[tok >> 5] + lp;
            if (slot < CAP)
                out[(size_t)tok * (N_EXP * CAP) + e * CAP + slot] = 1.0f;
        }
    }
}

// ---------------------------------------------------------------------------
extern "C" void kernel_launch(void* const* d_in, const int* in_sizes, int n_in,
                              void* d_out, int out_size) {
    const float* x = (const float*)d_in[0];   // [4096, 2048]
    const float* W = (const float*)d_in[1];   // [2048, 8]
    float* out = (float*)d_out;

    k_fused<<<GRID1, BLK1>>>(x, W, out);
    k_scatter<<<16, 256>>>(out);
}

// round 17
// speedup vs baseline: 1.1253x; 1.1253x over previous
#include <cuda_runtime.h>
#include <math.h>

#define N_TOK 4096
#define D_DIM 2048
#define N_EXP 8
#define TOPK  2
#define CAP   512
#define PITCH 2052                 // padded W smem row (floats)
#define BLK1  768                  // 24 warps: 16 GEMM + 8 fill
#define GRID1 128                  // 1 block/SM, single balanced wave

// Scratch (static device globals — no allocation)
__device__ unsigned int g_rec[N_TOK];     // packed: c0|lp0<<3|c1<<8|lp1<<11
__device__ int g_counts[16 * GRID1];      // [pair][block] counts

__device__ __forceinline__ unsigned long long fma2(
        unsigned long long a, unsigned long long b, unsigned long long c) {
    unsigned long long d;
    asm("fma.rn.f32x2 %0, %1, %2, %3;" : "=l"(d) : "l"(a), "l"(b), "l"(c));
    return d;
}

// ---------------------------------------------------------------------------
// Kernel 1 (byte-identical to R16 — proven, ~18.7us):
//   warps 0-15 : logits GEMM (2 tok/warp), top-2 + softmax, gates/indices.
//   warps 16-23: zero this block's 512 KB dispatcher slice concurrently.
//   epilogue   : warp 0 computes within-block (k,e) prefixes via ballot and
//                publishes packed per-token records + per-block counts.
// ---------------------------------------------------------------------------
__global__ __launch_bounds__(BLK1) void k_fused(
        const float* __restrict__ x,
        const float* __restrict__ W,
        float* __restrict__ out) {
    __shared__ float wt[N_EXP * PITCH];   // 65.7 KB
    __shared__ unsigned char s_c0[32], s_c1[32];

    int tid  = threadIdx.x;
    int lane = tid & 31;
    int wrp  = tid >> 5;
    int bid  = blockIdx.x;

    // stage ALL of W transposed: wt[e][d]  (all 24 warps help)
    for (int idx = tid; idx < D_DIM * N_EXP; idx += BLK1) {
        int d = idx >> 3;
        int e = idx & 7;
        wt[e * PITCH + d] = W[idx];
    }
    __syncthreads();

    if (wrp >= 16) {
        // ---------------- fill warps: zero 64 KB each ----------------
        int f = wrp - 16;
        float4* z4 = reinterpret_cast<float4*>(out);
        size_t base = (size_t)bid * 32768 + f * 4096 + lane;   // f4 units
        const float4 zero = make_float4(0.f, 0.f, 0.f, 0.f);
        #pragma unroll 8
        for (int i = 0; i < 128; i++)
            z4[base + i * 32] = zero;
    } else {
        // ---------------- GEMM warps: 2 tokens each ----------------
        int t0 = (bid * 16 + wrp) * 2;
        const ulonglong2* xr0 = reinterpret_cast<const ulonglong2*>(x) + (size_t)t0 * (D_DIM / 4);
        const ulonglong2* xr1 = xr0 + (D_DIM / 4);

        unsigned long long acc0[N_EXP] = {};
        unsigned long long acc1[N_EXP] = {};

        // double-buffered 2-j prefetch: 4 LDG.128 in flight per warp
        ulonglong2 xa[2][2], xb[2][2];
        xa[0][0] = xr0[lane];      xb[0][0] = xr1[lane];
        xa[0][1] = xr0[32 + lane]; xb[0][1] = xr1[32 + lane];

        #pragma unroll
        for (int jj = 0; jj < 8; jj++) {
            int cur = jj & 1, nxt = cur ^ 1;
            if (jj < 7) {
                int j2 = (jj + 1) * 2;
                xa[nxt][0] = xr0[(j2    ) * 32 + lane];
                xb[nxt][0] = xr1[(j2    ) * 32 + lane];
                xa[nxt][1] = xr0[(j2 + 1) * 32 + lane];
                xb[nxt][1] = xr1[(j2 + 1) * 32 + lane];
            }
            #pragma unroll
            for (int u = 0; u < 2; u++) {
                int dbase = ((jj * 2 + u) * 32 + lane) * 4;
                #pragma unroll
                for (int e = 0; e < N_EXP; e++) {
                    ulonglong2 w = *reinterpret_cast<const ulonglong2*>(&wt[e * PITCH + dbase]);
                    acc0[e] = fma2(xa[cur][u].x, w.x, acc0[e]);
                    acc0[e] = fma2(xa[cur][u].y, w.y, acc0[e]);
                    acc1[e] = fma2(xb[cur][u].x, w.x, acc1[e]);
                    acc1[e] = fma2(xb[cur][u].y, w.y, acc1[e]);
                }
            }
        }

        // horizontal add + butterfly reduce
        float logit[2][N_EXP];
        #pragma unroll
        for (int e = 0; e < N_EXP; e++) {
            float s0 = __uint_as_float((unsigned int)(acc0[e] & 0xffffffffull)) +
                       __uint_as_float((unsigned int)(acc0[e] >> 32));
            float s1 = __uint_as_float((unsigned int)(acc1[e] & 0xffffffffull)) +
                       __uint_as_float((unsigned int)(acc1[e] >> 32));
            #pragma unroll
            for (int off = 16; off > 0; off >>= 1) {
                s0 += __shfl_xor_sync(0xffffffffu, s0, off);
                s1 += __shfl_xor_sync(0xffffffffu, s1, off);
            }
            logit[0][e] = s0;
            logit[1][e] = s1;
        }

        if (lane == 0) {
            float* gate = out + (size_t)N_TOK * N_EXP * CAP;
            float* idxf = gate + N_TOK * TOPK;
            #pragma unroll
            for (int t = 0; t < 2; t++) {
                int tok = t0 + t;
                float best = -INFINITY, sec = -INFINITY;
                int bi = 0, si = 0;
                #pragma unroll
                for (int e = 0; e < N_EXP; e++) {
                    float v = logit[t][e];
                    if (v > best)     { sec = best; si = bi; best = v; bi = e; }
                    else if (v > sec) { sec = v;    si = e; }
                }
                float g0 = 1.0f / (1.0f + expf(sec - best));
                gate[tok * 2 + 0] = g0;
                gate[tok * 2 + 1] = 1.0f - g0;
                idxf[tok * 2 + 0] = (float)bi;
                idxf[tok * 2 + 1] = (float)si;
                int l = 2 * wrp + t;          // token index within block
                s_c0[l] = (unsigned char)bi;
                s_c1[l] = (unsigned char)si;
            }
        }
    }

    // ---- ballot epilogue: within-block prefixes + per-block counts ----
    __syncthreads();
    if (wrp == 0) {
        int c0 = s_c0[lane];                  // token bid*32+lane, k=0 choice
        int c1 = s_c1[lane];                  // k=1 choice
        unsigned int lt = (1u << lane) - 1u;
        int lp0 = 0, lp1 = 0, cnt0 = 0, cnt1 = 0;
        #pragma unroll
        for (int e = 0; e < N_EXP; e++) {
            unsigned int m0 = __ballot_sync(0xffffffffu, c0 == e);
            unsigned int m1 = __ballot_sync(0xffffffffu, c1 == e);
            if (c0 == e) lp0 = __popc(m0 & lt);
            if (c1 == e) lp1 = __popc(m1 & lt);
            if (lane == e) { cnt0 = __popc(m0); cnt1 = __popc(m1); }
        }
        g_rec[bid * 32 + lane] =
            (unsigned int)c0 | ((unsigned int)lp0 << 3) |
            ((unsigned int)c1 << 8) | ((unsigned int)lp1 << 11);
        if (lane < 8)  g_counts[lane * GRID1 + bid] = cnt0;        // pairs 0-7  (k=0)
        if (lane < 8)  g_counts[(8 + lane) * GRID1 + bid] = cnt1;  // pairs 8-15 (k=1)
    }
}

// ---------------------------------------------------------------------------
// Kernel 2: 16 blocks x 1024 threads (proven tail geometry).
// Warps 0-3: 128-block count prefix for this pair. Then 1024 threads scatter
// 4 tokens each (independent L2-hot g_rec loads).
// ---------------------------------------------------------------------------
__global__ __launch_bounds__(1024) void k_scatter(float* __restrict__ out) {
    int p = blockIdx.x;            // pair
    int k = p >> 3;
    int e = p & 7;
    int tid  = threadIdx.x;
    int lane = tid & 31;
    int w    = tid >> 5;

    __shared__ int bpre[GRID1];
    __shared__ int wsum[4];

    if (tid < GRID1) {
        int v = g_counts[p * GRID1 + tid];
        int inc = v;
        #pragma unroll
        for (int off = 1; off < 32; off <<= 1) {
            int u = __shfl_up_sync(0xffffffffu, inc, off);
            if (lane >= off) inc += u;
        }
        if (lane == 31) wsum[w] = inc;
        bpre[tid] = inc - v;                  // within-warp exclusive
    }
    __syncthreads();
    if (tid < GRID1) {
        int add = 0;
        #pragma unroll
        for (int i = 0; i < 4; i++)
            if (i < w) add += wsum[i];
        bpre[tid] += add;                     // full exclusive block prefix
    }
    __syncthreads();

    #pragma unroll
    for (int i = 0; i < 4; i++) {
        int tok = i * 1024 + tid;
        unsigned int r = g_rec[tok];
        int c  = k ? (int)((r >> 8) & 7)   : (int)(r & 7);
        int lp = k ? (int)((r >> 11) & 31) : (int)((r >> 3) & 31);
        if (c == e) {
            int slot = bpre[tok >> 5] + lp;
            if (slot < CAP)
                out[(size_t)tok * (N_EXP * CAP) + e * CAP + slot] = 1.0f;
        }
    }
}

// ---------------------------------------------------------------------------
extern "C" void kernel_launch(void* const* d_in, const int* in_sizes, int n_in,
                              void* d_out, int out_size) {
    const float* x = (const float*)d_in[0];   // [4096, 2048]
    const float* W = (const float*)d_in[1];   // [2048, 8]
    float* out = (float*)d_out;

    k_fused<<<GRID1, BLK1>>>(x, W, out);
    k_scatter<<<16, 1024>>>(out);
}